// round 5
// baseline (speedup 1.0000x reference)
#include <cuda_runtime.h>
#include <cuda_bf16.h>
#include <math.h>
#include <stdint.h>

// Problem constants
#define LAYERS 2
#define BATCH  4
#define SEQ    1024
#define HID    2048
#define NHEAD  16
#define HDIM   128
#define H3     (3*HID)
#define H4     (4*HID)
#define ROWS   (BATCH*SEQ)
#define NHEADS_TOT (BATCH*NHEAD)
#define EPSV   1e-5f

typedef __nv_bfloat16 bf16;

// ---------------------------------------------------------------------------
// Scratch (device globals)
// ---------------------------------------------------------------------------
__device__ float g_h   [(size_t)ROWS*HID];
__device__ float g_att [(size_t)ROWS*HID];
__device__ float g_h2  [(size_t)ROWS*HID];
__device__ float g_m2  [(size_t)ROWS*HID];
__device__ float g_scr [(size_t)NHEADS_TOT*SEQ*SEQ];
// bf16 split buffers
__device__ bf16 g_a0 [(size_t)ROWS*HID];
__device__ bf16 g_a1 [(size_t)ROWS*HID];
__device__ bf16 g_w0 [(size_t)H4*HID];
__device__ bf16 g_w1 [(size_t)H4*HID];
__device__ bf16 g_qkv0[(size_t)ROWS*H3];
__device__ bf16 g_qkv1[(size_t)ROWS*H3];
__device__ bf16 g_p0 [(size_t)NHEADS_TOT*SEQ*SEQ];
__device__ bf16 g_p1 [(size_t)NHEADS_TOT*SEQ*SEQ];
__device__ bf16 g_c0 [(size_t)ROWS*HID];
__device__ bf16 g_c1 [(size_t)ROWS*HID];
__device__ bf16 g_m1h[(size_t)ROWS*H4];
__device__ bf16 g_m1l[(size_t)ROWS*H4];

// ---------------------------------------------------------------------------
// Helpers
// ---------------------------------------------------------------------------
__device__ __forceinline__ uint32_t smem_u32(const void* p) {
    uint32_t a;
    asm("{ .reg .u64 t; cvta.to.shared.u64 t, %1; cvt.u32.u64 %0, t; }"
        : "=r"(a) : "l"(p));
    return a;
}
__device__ __forceinline__ void cp16(uint32_t dst, const void* src) {
    asm volatile("cp.async.cg.shared.global [%0], [%1], 16;"
                 :: "r"(dst), "l"(src) : "memory");
}
__device__ __forceinline__ void cp_commit() {
    asm volatile("cp.async.commit_group;" ::: "memory");
}
template<int N> __device__ __forceinline__ void cp_wait() {
    asm volatile("cp.async.wait_group %0;" :: "n"(N) : "memory");
}
__device__ __forceinline__ void mma16816(float* d, const uint32_t* a, const uint32_t* b) {
    asm volatile(
        "mma.sync.aligned.m16n8k16.row.col.f32.bf16.bf16.f32 "
        "{%0,%1,%2,%3}, {%4,%5,%6,%7}, {%8,%9}, {%0,%1,%2,%3};"
        : "+f"(d[0]), "+f"(d[1]), "+f"(d[2]), "+f"(d[3])
        : "r"(a[0]), "r"(a[1]), "r"(a[2]), "r"(a[3]), "r"(b[0]), "r"(b[1]));
}
__device__ __forceinline__ void ldsm4(uint32_t* r, uint32_t addr) {
    asm volatile("ldmatrix.sync.aligned.m8n8.x4.shared.b16 {%0,%1,%2,%3}, [%4];"
                 : "=r"(r[0]), "=r"(r[1]), "=r"(r[2]), "=r"(r[3]) : "r"(addr));
}
__device__ __forceinline__ void ldsm4t(uint32_t* r, uint32_t addr) {
    asm volatile("ldmatrix.sync.aligned.m8n8.x4.trans.shared.b16 {%0,%1,%2,%3}, [%4];"
                 : "=r"(r[0]), "=r"(r[1]), "=r"(r[2]), "=r"(r[3]) : "r"(addr));
}
__device__ __forceinline__ float gelu_f(float x) {
    float inner = 0.7978845608028654f * x * (1.0f + 0.044715f * x * x);
    return 0.5f * x * (1.0f + tanhf(inner));
}
__device__ __forceinline__ void st_split2(bf16* H, bf16* L, size_t off, float x, float y) {
    bf16 hx = __float2bfloat16(x), hy = __float2bfloat16(y);
    bf16 lx = __float2bfloat16(x - __bfloat162float(hx));
    bf16 ly = __float2bfloat16(y - __bfloat162float(hy));
    *reinterpret_cast<__nv_bfloat162*>(H + off) = __halves2bfloat162(hx, hy);
    *reinterpret_cast<__nv_bfloat162*>(L + off) = __halves2bfloat162(lx, ly);
}

// ---------------------------------------------------------------------------
// Block reductions
// ---------------------------------------------------------------------------
__device__ __forceinline__ float blockReduceSum256(float v) {
    __shared__ float sm[8];
    int lane = threadIdx.x & 31, w = threadIdx.x >> 5;
    #pragma unroll
    for (int o = 16; o > 0; o >>= 1) v += __shfl_xor_sync(0xffffffffu, v, o);
    if (lane == 0) sm[w] = v;
    __syncthreads();
    float r = sm[0];
    #pragma unroll
    for (int i = 1; i < 8; i++) r += sm[i];
    __syncthreads();
    return r;
}
__device__ __forceinline__ float blockReduceMax256(float v) {
    __shared__ float sm[8];
    int lane = threadIdx.x & 31, w = threadIdx.x >> 5;
    #pragma unroll
    for (int o = 16; o > 0; o >>= 1) v = fmaxf(v, __shfl_xor_sync(0xffffffffu, v, o));
    if (lane == 0) sm[w] = v;
    __syncthreads();
    float r = sm[0];
    #pragma unroll
    for (int i = 1; i < 8; i++) r = fmaxf(r, sm[i]);
    __syncthreads();
    return r;
}

// ---------------------------------------------------------------------------
// LayerNorm variants
// ---------------------------------------------------------------------------
__global__ __launch_bounds__(256) void ln_kernel(
    const float* __restrict__ x, const float* __restrict__ gamma,
    const float* __restrict__ beta, const float* __restrict__ res,
    float* __restrict__ out)
{
    const int row = blockIdx.x;
    const int tid = threadIdx.x;
    const float* xr = x + (size_t)row * HID;

    float v[8];
    float s = 0.f;
    #pragma unroll
    for (int i = 0; i < 8; i++) { v[i] = xr[i*256 + tid]; s += v[i]; }
    s = blockReduceSum256(s);
    const float mean = s * (1.0f / HID);

    float q = 0.f;
    #pragma unroll
    for (int i = 0; i < 8; i++) { float d = v[i] - mean; q += d * d; }
    q = blockReduceSum256(q);
    const float rstd = rsqrtf(q * (1.0f / HID) + EPSV);

    float* orow = out + (size_t)row * HID;
    const float* rrow = res + (size_t)row * HID;
    #pragma unroll
    for (int i = 0; i < 8; i++) {
        int c = i*256 + tid;
        orow[c] = rrow[c] + (v[i] - mean) * rstd * gamma[c] + beta[c];
    }
}

__global__ __launch_bounds__(256) void ln_split_kernel(
    const float* __restrict__ x, const float* __restrict__ gamma,
    const float* __restrict__ beta, bf16* __restrict__ hi, bf16* __restrict__ lo)
{
    const int row = blockIdx.x;
    const int tid = threadIdx.x;
    const float* xr = x + (size_t)row * HID;
    const int cb = tid * 8;

    float v[8];
    *reinterpret_cast<float4*>(v)     = *reinterpret_cast<const float4*>(xr + cb);
    *reinterpret_cast<float4*>(v + 4) = *reinterpret_cast<const float4*>(xr + cb + 4);
    float s = 0.f;
    #pragma unroll
    for (int i = 0; i < 8; i++) s += v[i];
    s = blockReduceSum256(s);
    const float mean = s * (1.0f / HID);

    float q = 0.f;
    #pragma unroll
    for (int i = 0; i < 8; i++) { float d = v[i] - mean; q += d * d; }
    q = blockReduceSum256(q);
    const float rstd = rsqrtf(q * (1.0f / HID) + EPSV);

    const size_t ob = (size_t)row * HID + cb;
    #pragma unroll
    for (int i = 0; i < 8; i += 2) {
        float o0 = (v[i]   - mean) * rstd * gamma[cb+i]   + beta[cb+i];
        float o1 = (v[i+1] - mean) * rstd * gamma[cb+i+1] + beta[cb+i+1];
        st_split2(hi, lo, ob + i, o0, o1);
    }
}

// ---------------------------------------------------------------------------
// fp32 -> bf16 hi/lo split (weights)
// ---------------------------------------------------------------------------
__global__ __launch_bounds__(256) void split_fp32_bf16(
    const float* __restrict__ src, bf16* __restrict__ hi,
    bf16* __restrict__ lo, int n4)
{
    int i = blockIdx.x * 256 + threadIdx.x;
    if (i >= n4) return;
    float4 v = reinterpret_cast<const float4*>(src)[i];
    st_split2(hi, lo, (size_t)i * 4,     v.x, v.y);
    st_split2(hi, lo, (size_t)i * 4 + 2, v.z, v.w);
}

// ---------------------------------------------------------------------------
// Common 128x128 split-3 bf16 mma body. 4-stage cp.async circular pipeline,
// ONE __syncthreads per BK=32 iteration.
// smem: 4 stages x 40960B; tile slots of 10240B at A0/A1/B0/B1.
// ---------------------------------------------------------------------------
#define STAGE_BYTES 40960
#define NSTAGES 4
#define GEMM_SMEM_DYN (NSTAGES*STAGE_BYTES)

template<int GELU, int HAS_BIAS, int OUT_SPLIT, int BTRANS>
__device__ __forceinline__ void gemm128_body(
    const bf16* __restrict__ A0b, const bf16* __restrict__ A1b, int lda,
    const bf16* __restrict__ B0b, const bf16* __restrict__ B1b, int ldb,
    const float* __restrict__ bias, float scale,
    float* __restrict__ Cf, bf16* __restrict__ Ch, bf16* __restrict__ Cl,
    int ldc, int K)
{
    extern __shared__ uint32_t smw[];
    const uint32_t smbase = smem_u32(smw);

    const int tid = threadIdx.x;
    const int wid = tid >> 5, lane = tid & 31;
    const int wm = wid & 3, wn = wid >> 2;
    const int g = lane >> 2, c = lane & 3;

    const char* pA0 = (const char*)A0b;
    const char* pA1 = (const char*)A1b;
    const char* pB0 = (const char*)B0b;
    const char* pB1 = (const char*)B1b;
    const size_t la = (size_t)lda * 2, lb = (size_t)ldb * 2;

    auto load_stage = [&](int it, int buf) {
        const uint32_t sb = smbase + (uint32_t)buf * STAGE_BYTES;
        if (BTRANS == 0) {
            #pragma unroll
            for (int i = 0; i < 8; i++) {
                int idx = tid + i * 256;
                int t  = idx >> 9;
                int r  = (idx >> 2) & 127;
                int ch = idx & 3;
                const char* base = (t == 0) ? pA0 : (t == 1) ? pA1 : (t == 2) ? pB0 : pB1;
                size_t stride = (t < 2) ? la : lb;
                cp16(sb + (uint32_t)(t * 10240 + r * 80 + ch * 16),
                     base + (size_t)r * stride + (size_t)it * 64 + ch * 16);
            }
        } else {
            #pragma unroll
            for (int i = 0; i < 4; i++) {
                int idx = tid + i * 256;
                int sp = idx >> 9;
                int r  = (idx >> 2) & 127;
                int ch = idx & 3;
                const char* base = sp ? pA1 : pA0;
                cp16(sb + (uint32_t)(sp * 10240 + r * 80 + ch * 16),
                     base + (size_t)r * la + (size_t)it * 64 + ch * 16);
            }
            #pragma unroll
            for (int i = 0; i < 4; i++) {
                int idx = tid + i * 256;
                int sp = idx >> 9;
                int r  = (idx >> 4) & 31;
                int ch = idx & 15;
                const char* base = sp ? pB1 : pB0;
                cp16(sb + (uint32_t)(20480 + sp * 10240 + r * 256 + ((ch ^ (r & 7)) * 16)),
                     base + (size_t)(it * 32 + r) * lb + ch * 16);
            }
        }
    };

    const uint32_t a_off = (uint32_t)((wm * 32 + (lane & 15)) * 80 + ((lane & 16) ? 16 : 0));
    const uint32_t b_nt  = (uint32_t)((wn * 64 + (lane & 7) + ((lane & 16) ? 8 : 0)) * 80
                                      + ((lane & 8) ? 16 : 0));
    const int t0l = lane & 15;
    const int cb3 = wn * 8 + ((lane & 16) ? 1 : 0);

    float acc[2][8][4];
    #pragma unroll
    for (int i = 0; i < 2; i++)
        #pragma unroll
        for (int j = 0; j < 8; j++)
            #pragma unroll
            for (int k = 0; k < 4; k++) acc[i][j][k] = 0.f;

    const int nIter = K >> 5;

    // prologue: prefetch up to NSTAGES-1 stages
    #pragma unroll
    for (int s = 0; s < NSTAGES - 1; s++) {
        if (s < nIter) load_stage(s, s);
        cp_commit();
    }

    for (int it = 0; it < nIter; ++it) {
        cp_wait<NSTAGES - 2>();     // stage `it` resident
        __syncthreads();            // visible to all warps; prior stage fully read

        const uint32_t sb = smbase + (uint32_t)(it & (NSTAGES - 1)) * STAGE_BYTES;
        #pragma unroll
        for (int ks = 0; ks < 2; ++ks) {
            uint32_t a0r[2][4], a1r[2][4];
            #pragma unroll
            for (int fm = 0; fm < 2; ++fm) {
                uint32_t ao = sb + a_off + fm * 1280 + ks * 32;
                ldsm4(a0r[fm], ao);
                ldsm4(a1r[fm], ao + 10240);
            }
            #pragma unroll
            for (int fn2 = 0; fn2 < 4; ++fn2) {
                uint32_t b0r[4], b1r[4];
                if (BTRANS == 0) {
                    uint32_t bo = sb + 20480 + b_nt + fn2 * 1280 + ks * 32;
                    ldsm4(b0r, bo);
                    ldsm4(b1r, bo + 10240);
                } else {
                    int t = ks * 16 + t0l;
                    uint32_t bo = sb + 20480
                        + (uint32_t)(t * 256 + (((cb3 + fn2 * 2) ^ (t & 7)) * 16));
                    ldsm4t(b0r, bo);
                    ldsm4t(b1r, bo + 10240);
                }
                #pragma unroll
                for (int fm = 0; fm < 2; ++fm) {
                    mma16816(acc[fm][2*fn2],   a0r[fm], b0r);
                    mma16816(acc[fm][2*fn2],   a0r[fm], b1r);
                    mma16816(acc[fm][2*fn2],   a1r[fm], b0r);
                    mma16816(acc[fm][2*fn2+1], a0r[fm], b0r + 2);
                    mma16816(acc[fm][2*fn2+1], a0r[fm], b1r + 2);
                    mma16816(acc[fm][2*fn2+1], a1r[fm], b0r + 2);
                }
            }
        }

        // prefetch stage it+NSTAGES-1 into slot last read at iter it-1
        if (it + NSTAGES - 1 < nIter)
            load_stage(it + NSTAGES - 1, (it + NSTAGES - 1) & (NSTAGES - 1));
        cp_commit();
    }

    // epilogue
    #pragma unroll
    for (int fm = 0; fm < 2; ++fm) {
        const int r0 = wm * 32 + fm * 16 + g;
        #pragma unroll
        for (int fn = 0; fn < 8; ++fn) {
            const int col = wn * 64 + fn * 8 + 2 * c;
            float bv0 = 0.f, bv1 = 0.f;
            if (HAS_BIAS) { bv0 = __ldg(&bias[col]); bv1 = __ldg(&bias[col + 1]); }
            float o0 = acc[fm][fn][0] * scale + bv0;
            float o1 = acc[fm][fn][1] * scale + bv1;
            float o2 = acc[fm][fn][2] * scale + bv0;
            float o3 = acc[fm][fn][3] * scale + bv1;
            if (GELU) { o0 = gelu_f(o0); o1 = gelu_f(o1); o2 = gelu_f(o2); o3 = gelu_f(o3); }
            const size_t off0 = (size_t)r0 * ldc + col;
            const size_t off1 = (size_t)(r0 + 8) * ldc + col;
            if (OUT_SPLIT) {
                st_split2(Ch, Cl, off0, o0, o1);
                st_split2(Ch, Cl, off1, o2, o3);
            } else {
                *reinterpret_cast<float2*>(Cf + off0) = make_float2(o0, o1);
                *reinterpret_cast<float2*>(Cf + off1) = make_float2(o2, o3);
            }
        }
    }
}

// ---------------------------------------------------------------------------
// Kernel wrappers
// ---------------------------------------------------------------------------
template<int GELU, int OUT_SPLIT>
__global__ __launch_bounds__(256, 1) void k_gemm(
    const bf16* __restrict__ A0, const bf16* __restrict__ A1,
    const bf16* __restrict__ B0, const bf16* __restrict__ B1,
    const float* __restrict__ bias,
    float* __restrict__ Cf, bf16* __restrict__ Ch, bf16* __restrict__ Cl,
    int M, int N, int K)
{
    const int bm = blockIdx.y * 128;
    const int bn = blockIdx.x * 128;
    const size_t aoff = (size_t)bm * K;
    const size_t boff = (size_t)bn * K;
    const size_t coff = (size_t)bm * N + bn;
    gemm128_body<GELU, 1, OUT_SPLIT, 0>(
        A0 + aoff, A1 + aoff, K, B0 + boff, B1 + boff, K,
        bias + bn, 1.0f,
        OUT_SPLIT ? nullptr : (Cf + coff),
        OUT_SPLIT ? (Ch + coff) : nullptr,
        OUT_SPLIT ? (Cl + coff) : nullptr,
        N, K);
}

__global__ __launch_bounds__(256, 1) void k_scores(
    const bf16* __restrict__ q0, const bf16* __restrict__ q1,
    float* __restrict__ scr)
{
    const int tt = blockIdx.x, st = blockIdx.y;
    if (tt > st) return;
    const int hd = blockIdx.z, b = hd >> 4, n = hd & 15;
    const size_t qoff = ((size_t)b * SEQ + (size_t)st * 128) * H3 + (size_t)n * HDIM;
    const size_t koff = ((size_t)b * SEQ + (size_t)tt * 128) * H3 + HID + (size_t)n * HDIM;
    float* C = scr + ((size_t)hd * SEQ + (size_t)st * 128) * SEQ + (size_t)tt * 128;
    gemm128_body<0, 0, 0, 0>(
        q0 + qoff, q1 + qoff, H3, q0 + koff, q1 + koff, H3,
        nullptr, 0.08838834764831845f, C, nullptr, nullptr, SEQ, HDIM);
}

__global__ __launch_bounds__(256, 1) void k_pv(
    const bf16* __restrict__ p0, const bf16* __restrict__ p1,
    const bf16* __restrict__ v0, const bf16* __restrict__ v1,
    bf16* __restrict__ ch, bf16* __restrict__ cl)
{
    const int st = blockIdx.x, hd = blockIdx.y, b = hd >> 4, n = hd & 15;
    const size_t poff = ((size_t)hd * SEQ + (size_t)st * 128) * SEQ;
    const size_t voff = (size_t)b * SEQ * H3 + 2 * HID + (size_t)n * HDIM;
    const size_t coff = ((size_t)b * SEQ + (size_t)st * 128) * HID + (size_t)n * HDIM;
    gemm128_body<0, 0, 1, 1>(
        p0 + poff, p1 + poff, SEQ, v0 + voff, v1 + voff, H3,
        nullptr, 1.0f, nullptr, ch + coff, cl + coff, HID, (st + 1) * 128);
}

// ---------------------------------------------------------------------------
// Causal softmax: fp32 scores -> split bf16 probs, zero-filled to tile end
// ---------------------------------------------------------------------------
__global__ __launch_bounds__(256) void softmax_split(
    const float* __restrict__ scr, bf16* __restrict__ p0, bf16* __restrict__ p1)
{
    const int s  = blockIdx.x;
    const int hd = blockIdx.y;
    const size_t rb = ((size_t)hd * SEQ + s) * SEQ;
    const float* row = scr + rb;
    const int len = s + 1;
    const int base = threadIdx.x * 4;

    float4 v = *reinterpret_cast<const float4*>(row + base);
    float e[4] = {v.x, v.y, v.z, v.w};
    float mx = -1e30f;
    #pragma unroll
    for (int j = 0; j < 4; j++) {
        if (base + j >= len) e[j] = -1e30f;
        mx = fmaxf(mx, e[j]);
    }
    mx = blockReduceMax256(mx);

    float sum = 0.f;
    #pragma unroll
    for (int j = 0; j < 4; j++) {
        e[j] = (base + j < len) ? expf(e[j] - mx) : 0.f;
        sum += e[j];
    }
    sum = blockReduceSum256(sum);
    const float inv = 1.0f / sum;

    const int tile_end = ((s >> 7) + 1) << 7;
    if (base < tile_end) {
        float o0 = e[0] * inv, o1 = e[1] * inv, o2 = e[2] * inv, o3 = e[3] * inv;
        st_split2(p0, p1, rb + base,     o0, o1);
        st_split2(p0, p1, rb + base + 2, o2, o3);
    }
}

// ---------------------------------------------------------------------------
// Host side
// ---------------------------------------------------------------------------
static float* symaddrf(const void* sym) {
    void* p = nullptr; cudaGetSymbolAddress(&p, sym); return (float*)p;
}
static bf16* symaddrb(const void* sym) {
    void* p = nullptr; cudaGetSymbolAddress(&p, sym); return (bf16*)p;
}
static void split_launch(const float* s, bf16* hi, bf16* lo, size_t n) {
    int n4 = (int)(n / 4);
    split_fp32_bf16<<<(n4 + 255) / 256, 256>>>(s, hi, lo, n4);
}

extern "C" void kernel_launch(void* const* d_in, const int* in_sizes, int n_in,
                              void* d_out, int out_size)
{
    const float* hidden  = (const float*)d_in[0];
    const float* qkv_w   = (const float*)d_in[2];
    const float* qkv_b   = (const float*)d_in[3];
    const float* dense_w = (const float*)d_in[4];
    const float* dense_b = (const float*)d_in[5];
    const float* mlp_w1  = (const float*)d_in[6];
    const float* mlp_b1  = (const float*)d_in[7];
    const float* mlp_w2  = (const float*)d_in[8];
    const float* mlp_b2  = (const float*)d_in[9];
    const float* ln_in_g   = (const float*)d_in[10];
    const float* ln_in_b   = (const float*)d_in[11];
    const float* ln_post_g = (const float*)d_in[12];
    const float* ln_post_b = (const float*)d_in[13];
    const float* ln_s1_g   = (const float*)d_in[14];
    const float* ln_s1_b   = (const float*)d_in[15];
    const float* ln_s2_g   = (const float*)d_in[16];
    const float* ln_s2_b   = (const float*)d_in[17];

    cudaFuncSetAttribute(k_gemm<0,0>, cudaFuncAttributeMaxDynamicSharedMemorySize, GEMM_SMEM_DYN);
    cudaFuncSetAttribute(k_gemm<0,1>, cudaFuncAttributeMaxDynamicSharedMemorySize, GEMM_SMEM_DYN);
    cudaFuncSetAttribute(k_gemm<1,1>, cudaFuncAttributeMaxDynamicSharedMemorySize, GEMM_SMEM_DYN);
    cudaFuncSetAttribute(k_scores,    cudaFuncAttributeMaxDynamicSharedMemorySize, GEMM_SMEM_DYN);
    cudaFuncSetAttribute(k_pv,        cudaFuncAttributeMaxDynamicSharedMemorySize, GEMM_SMEM_DYN);

    float* h   = symaddrf(g_h);
    float* att = symaddrf(g_att);
    float* h2  = symaddrf(g_h2);
    float* m2  = symaddrf(g_m2);
    float* scr = symaddrf(g_scr);
    bf16* a0 = symaddrb(g_a0);   bf16* a1 = symaddrb(g_a1);
    bf16* w0 = symaddrb(g_w0);   bf16* w1 = symaddrb(g_w1);
    bf16* q0 = symaddrb(g_qkv0); bf16* q1 = symaddrb(g_qkv1);
    bf16* p0 = symaddrb(g_p0);   bf16* p1 = symaddrb(g_p1);
    bf16* c0 = symaddrb(g_c0);   bf16* c1 = symaddrb(g_c1);
    bf16* m1h = symaddrb(g_m1h); bf16* m1l = symaddrb(g_m1l);
    float* out = (float*)d_out;

    for (int l = 0; l < LAYERS; l++) {
        const float* hin = (l == 0) ? hidden : h;
        const float* l_qkv_w   = qkv_w   + (size_t)l * H3 * HID;
        const float* l_qkv_b   = qkv_b   + (size_t)l * H3;
        const float* l_dense_w = dense_w + (size_t)l * HID * HID;
        const float* l_dense_b = dense_b + (size_t)l * HID;
        const float* l_w1      = mlp_w1  + (size_t)l * H4 * HID;
        const float* l_b1      = mlp_b1  + (size_t)l * H4;
        const float* l_w2      = mlp_w2  + (size_t)l * HID * H4;
        const float* l_b2      = mlp_b2  + (size_t)l * HID;

        // x = LN_in(h) -> split
        ln_split_kernel<<<ROWS, 256>>>(hin, ln_in_g + l*HID, ln_in_b + l*HID, a0, a1);

        // qkv = x @ qkv_w^T + b  -> split bf16
        split_launch(l_qkv_w, w0, w1, (size_t)H3 * HID);
        k_gemm<0,1><<<dim3(H3/128, ROWS/128), 256, GEMM_SMEM_DYN>>>(
            a0, a1, w0, w1, l_qkv_b, nullptr, q0, q1, ROWS, H3, HID);

        // attention on tensor cores
        k_scores<<<dim3(8, 8, NHEADS_TOT), 256, GEMM_SMEM_DYN>>>(q0, q1, scr);
        softmax_split<<<dim3(SEQ, NHEADS_TOT), 256>>>(scr, p0, p1);
        k_pv<<<dim3(8, NHEADS_TOT), 256, GEMM_SMEM_DYN>>>(p0, p1, q0, q1, c0, c1);

        // attn_out = ctx @ dense_w^T + b  (fp32)
        split_launch(l_dense_w, w0, w1, (size_t)HID * HID);
        k_gemm<0,0><<<dim3(HID/128, ROWS/128), 256, GEMM_SMEM_DYN>>>(
            c0, c1, w0, w1, l_dense_b, att, nullptr, nullptr, ROWS, HID, HID);

        // h2 = h + LN_s1(attn_out)
        ln_kernel<<<ROWS, 256>>>(att, ln_s1_g + l*HID, ln_s1_b + l*HID, hin, h2);

        // y = LN_post(h2) -> split
        ln_split_kernel<<<ROWS, 256>>>(h2, ln_post_g + l*HID, ln_post_b + l*HID, a0, a1);

        // m1 = gelu(y @ w1^T + b1) -> split
        split_launch(l_w1, w0, w1, (size_t)H4 * HID);
        k_gemm<1,1><<<dim3(H4/128, ROWS/128), 256, GEMM_SMEM_DYN>>>(
            a0, a1, w0, w1, l_b1, nullptr, m1h, m1l, ROWS, H4, HID);

        // m2 = m1 @ w2^T + b2 (fp32)
        split_launch(l_w2, w0, w1, (size_t)HID * H4);
        k_gemm<0,0><<<dim3(HID/128, ROWS/128), 256, GEMM_SMEM_DYN>>>(
            m1h, m1l, w0, w1, l_b2, m2, nullptr, nullptr, ROWS, HID, H4);

        // h = h2 + LN_s2(m2)
        ln_kernel<<<ROWS, 256>>>(m2, ln_s2_g + l*HID, ln_s2_b + l*HID, h2, h);
    }

    cudaMemcpyAsync(out, h, (size_t)ROWS * HID * sizeof(float),
                    cudaMemcpyDeviceToDevice, 0);
}

// round 6
// speedup vs baseline: 1.1928x; 1.1928x over previous
#include <cuda_runtime.h>
#include <cuda_bf16.h>
#include <math.h>
#include <stdint.h>

// Problem constants
#define LAYERS 2
#define BATCH  4
#define SEQ    1024
#define HID    2048
#define NHEAD  16
#define HDIM   128
#define H3     (3*HID)
#define H4     (4*HID)
#define ROWS   (BATCH*SEQ)
#define NHEADS_TOT (BATCH*NHEAD)
#define EPSV   1e-5f

typedef __nv_bfloat16 bf16;

// ---------------------------------------------------------------------------
// Scratch (device globals)
// ---------------------------------------------------------------------------
__device__ float g_h   [(size_t)ROWS*HID];
__device__ float g_att [(size_t)ROWS*HID];
__device__ float g_h2  [(size_t)ROWS*HID];
__device__ float g_m2  [(size_t)ROWS*HID];
__device__ float g_scr [(size_t)NHEADS_TOT*SEQ*SEQ];
// bf16 split buffers
__device__ bf16 g_a0 [(size_t)ROWS*HID];
__device__ bf16 g_a1 [(size_t)ROWS*HID];
__device__ bf16 g_w0 [(size_t)H4*HID];
__device__ bf16 g_w1 [(size_t)H4*HID];
__device__ bf16 g_qkv0[(size_t)ROWS*H3];
__device__ bf16 g_qkv1[(size_t)ROWS*H3];
__device__ bf16 g_p0 [(size_t)NHEADS_TOT*SEQ*SEQ];
__device__ bf16 g_p1 [(size_t)NHEADS_TOT*SEQ*SEQ];
__device__ bf16 g_c0 [(size_t)ROWS*HID];
__device__ bf16 g_c1 [(size_t)ROWS*HID];
__device__ bf16 g_m1h[(size_t)ROWS*H4];
__device__ bf16 g_m1l[(size_t)ROWS*H4];

// ---------------------------------------------------------------------------
// Helpers
// ---------------------------------------------------------------------------
__device__ __forceinline__ uint32_t smem_u32(const void* p) {
    uint32_t a;
    asm("{ .reg .u64 t; cvta.to.shared.u64 t, %1; cvt.u32.u64 %0, t; }"
        : "=r"(a) : "l"(p));
    return a;
}
__device__ __forceinline__ void cp16(uint32_t dst, const void* src) {
    asm volatile("cp.async.cg.shared.global [%0], [%1], 16;"
                 :: "r"(dst), "l"(src) : "memory");
}
__device__ __forceinline__ void cp_commit() {
    asm volatile("cp.async.commit_group;" ::: "memory");
}
template<int N> __device__ __forceinline__ void cp_wait() {
    asm volatile("cp.async.wait_group %0;" :: "n"(N) : "memory");
}
__device__ __forceinline__ void mma16816(float* d, const uint32_t* a, const uint32_t* b) {
    asm volatile(
        "mma.sync.aligned.m16n8k16.row.col.f32.bf16.bf16.f32 "
        "{%0,%1,%2,%3}, {%4,%5,%6,%7}, {%8,%9}, {%0,%1,%2,%3};"
        : "+f"(d[0]), "+f"(d[1]), "+f"(d[2]), "+f"(d[3])
        : "r"(a[0]), "r"(a[1]), "r"(a[2]), "r"(a[3]), "r"(b[0]), "r"(b[1]));
}
__device__ __forceinline__ void ldsm4(uint32_t* r, uint32_t addr) {
    asm volatile("ldmatrix.sync.aligned.m8n8.x4.shared.b16 {%0,%1,%2,%3}, [%4];"
                 : "=r"(r[0]), "=r"(r[1]), "=r"(r[2]), "=r"(r[3]) : "r"(addr));
}
__device__ __forceinline__ void ldsm4t(uint32_t* r, uint32_t addr) {
    asm volatile("ldmatrix.sync.aligned.m8n8.x4.trans.shared.b16 {%0,%1,%2,%3}, [%4];"
                 : "=r"(r[0]), "=r"(r[1]), "=r"(r[2]), "=r"(r[3]) : "r"(addr));
}
__device__ __forceinline__ float gelu_f(float x) {
    float inner = 0.7978845608028654f * x * (1.0f + 0.044715f * x * x);
    return 0.5f * x * (1.0f + tanhf(inner));
}
__device__ __forceinline__ void st_split2(bf16* H, bf16* L, size_t off, float x, float y) {
    bf16 hx = __float2bfloat16(x), hy = __float2bfloat16(y);
    bf16 lx = __float2bfloat16(x - __bfloat162float(hx));
    bf16 ly = __float2bfloat16(y - __bfloat162float(hy));
    *reinterpret_cast<__nv_bfloat162*>(H + off) = __halves2bfloat162(hx, hy);
    *reinterpret_cast<__nv_bfloat162*>(L + off) = __halves2bfloat162(lx, ly);
}

// ---------------------------------------------------------------------------
// Block reductions
// ---------------------------------------------------------------------------
__device__ __forceinline__ float blockReduceSum256(float v) {
    __shared__ float sm[8];
    int lane = threadIdx.x & 31, w = threadIdx.x >> 5;
    #pragma unroll
    for (int o = 16; o > 0; o >>= 1) v += __shfl_xor_sync(0xffffffffu, v, o);
    if (lane == 0) sm[w] = v;
    __syncthreads();
    float r = sm[0];
    #pragma unroll
    for (int i = 1; i < 8; i++) r += sm[i];
    __syncthreads();
    return r;
}
__device__ __forceinline__ float blockReduceMax256(float v) {
    __shared__ float sm[8];
    int lane = threadIdx.x & 31, w = threadIdx.x >> 5;
    #pragma unroll
    for (int o = 16; o > 0; o >>= 1) v = fmaxf(v, __shfl_xor_sync(0xffffffffu, v, o));
    if (lane == 0) sm[w] = v;
    __syncthreads();
    float r = sm[0];
    #pragma unroll
    for (int i = 1; i < 8; i++) r = fmaxf(r, sm[i]);
    __syncthreads();
    return r;
}

// ---------------------------------------------------------------------------
// LayerNorm variants
// ---------------------------------------------------------------------------
__global__ __launch_bounds__(256) void ln_kernel(
    const float* __restrict__ x, const float* __restrict__ gamma,
    const float* __restrict__ beta, const float* __restrict__ res,
    float* __restrict__ out)
{
    const int row = blockIdx.x;
    const int tid = threadIdx.x;
    const float* xr = x + (size_t)row * HID;

    float v[8];
    float s = 0.f;
    #pragma unroll
    for (int i = 0; i < 8; i++) { v[i] = xr[i*256 + tid]; s += v[i]; }
    s = blockReduceSum256(s);
    const float mean = s * (1.0f / HID);

    float q = 0.f;
    #pragma unroll
    for (int i = 0; i < 8; i++) { float d = v[i] - mean; q += d * d; }
    q = blockReduceSum256(q);
    const float rstd = rsqrtf(q * (1.0f / HID) + EPSV);

    float* orow = out + (size_t)row * HID;
    const float* rrow = res + (size_t)row * HID;
    #pragma unroll
    for (int i = 0; i < 8; i++) {
        int c = i*256 + tid;
        orow[c] = rrow[c] + (v[i] - mean) * rstd * gamma[c] + beta[c];
    }
}

__global__ __launch_bounds__(256) void ln_split_kernel(
    const float* __restrict__ x, const float* __restrict__ gamma,
    const float* __restrict__ beta, bf16* __restrict__ hi, bf16* __restrict__ lo)
{
    const int row = blockIdx.x;
    const int tid = threadIdx.x;
    const float* xr = x + (size_t)row * HID;
    const int cb = tid * 8;

    float v[8];
    *reinterpret_cast<float4*>(v)     = *reinterpret_cast<const float4*>(xr + cb);
    *reinterpret_cast<float4*>(v + 4) = *reinterpret_cast<const float4*>(xr + cb + 4);
    float s = 0.f;
    #pragma unroll
    for (int i = 0; i < 8; i++) s += v[i];
    s = blockReduceSum256(s);
    const float mean = s * (1.0f / HID);

    float q = 0.f;
    #pragma unroll
    for (int i = 0; i < 8; i++) { float d = v[i] - mean; q += d * d; }
    q = blockReduceSum256(q);
    const float rstd = rsqrtf(q * (1.0f / HID) + EPSV);

    const size_t ob = (size_t)row * HID + cb;
    #pragma unroll
    for (int i = 0; i < 8; i += 2) {
        float o0 = (v[i]   - mean) * rstd * gamma[cb+i]   + beta[cb+i];
        float o1 = (v[i+1] - mean) * rstd * gamma[cb+i+1] + beta[cb+i+1];
        st_split2(hi, lo, ob + i, o0, o1);
    }
}

// ---------------------------------------------------------------------------
// fp32 -> bf16 hi/lo split (weights)
// ---------------------------------------------------------------------------
__global__ __launch_bounds__(256) void split_fp32_bf16(
    const float* __restrict__ src, bf16* __restrict__ hi,
    bf16* __restrict__ lo, int n4)
{
    int i = blockIdx.x * 256 + threadIdx.x;
    if (i >= n4) return;
    float4 v = reinterpret_cast<const float4*>(src)[i];
    st_split2(hi, lo, (size_t)i * 4,     v.x, v.y);
    st_split2(hi, lo, (size_t)i * 4 + 2, v.z, v.w);
}

// ---------------------------------------------------------------------------
// Common 128x128 split-3 bf16 mma body.
// 3-stage cp.async circular pipeline, compact 64B rows with chunk-XOR swizzle
// (chunk' = chunk ^ ((row>>1)&3)) -> 32KB stages, 96KB total, 2 CTAs/SM,
// ONE __syncthreads per BK=32 iteration.
// Stage layout: A0 @0, A1 @8192, B0 @16384, B1 @24576 (8KB tile slots).
// ---------------------------------------------------------------------------
#define STAGE_BYTES 32768
#define NSTAGES 3
#define GEMM_SMEM_DYN (NSTAGES*STAGE_BYTES)

template<int GELU, int HAS_BIAS, int OUT_SPLIT, int BTRANS>
__device__ __forceinline__ void gemm128_body(
    const bf16* __restrict__ A0b, const bf16* __restrict__ A1b, int lda,
    const bf16* __restrict__ B0b, const bf16* __restrict__ B1b, int ldb,
    const float* __restrict__ bias, float scale,
    float* __restrict__ Cf, bf16* __restrict__ Ch, bf16* __restrict__ Cl,
    int ldc, int K)
{
    extern __shared__ uint32_t smw[];
    const uint32_t smbase = smem_u32(smw);

    const int tid = threadIdx.x;
    const int wid = tid >> 5, lane = tid & 31;
    const int wm = wid & 3, wn = wid >> 2;
    const int g = lane >> 2, c = lane & 3;

    const char* pA0 = (const char*)A0b;
    const char* pA1 = (const char*)A1b;
    const char* pB0 = (const char*)B0b;
    const char* pB1 = (const char*)B1b;
    const size_t la = (size_t)lda * 2, lb = (size_t)ldb * 2;

    auto load_stage = [&](int it, uint32_t sb) {
        if (BTRANS == 0) {
            #pragma unroll
            for (int i = 0; i < 8; i++) {
                int idx = tid + i * 256;
                int t  = idx >> 9;
                int r  = (idx >> 2) & 127;
                int ch = idx & 3;
                const char* base = (t == 0) ? pA0 : (t == 1) ? pA1 : (t == 2) ? pB0 : pB1;
                size_t stride = (t < 2) ? la : lb;
                cp16(sb + (uint32_t)(t * 8192 + r * 64 + ((ch ^ ((r >> 1) & 3)) << 4)),
                     base + (size_t)r * stride + (size_t)it * 64 + ch * 16);
            }
        } else {
            #pragma unroll
            for (int i = 0; i < 4; i++) {       // A (P): 2 splits x 128 rows x 4 chunks
                int idx = tid + i * 256;
                int sp = idx >> 9;
                int r  = (idx >> 2) & 127;
                int ch = idx & 3;
                const char* base = sp ? pA1 : pA0;
                cp16(sb + (uint32_t)(sp * 8192 + r * 64 + ((ch ^ ((r >> 1) & 3)) << 4)),
                     base + (size_t)r * la + (size_t)it * 64 + ch * 16);
            }
            #pragma unroll
            for (int i = 0; i < 4; i++) {       // B (V): 2 splits x 32 rows x 16 chunks
                int idx = tid + i * 256;
                int sp = idx >> 9;
                int r  = (idx >> 4) & 31;
                int ch = idx & 15;
                const char* base = sp ? pB1 : pB0;
                cp16(sb + (uint32_t)(16384 + sp * 8192 + r * 256 + ((ch ^ (r & 7)) * 16)),
                     base + (size_t)(it * 32 + r) * lb + ch * 16);
            }
        }
    };

    // per-thread ldmatrix constants
    const int ar   = (lane & 15);               // A row within 16-row frag
    const int sw_a = (ar >> 1) & 3;             // A chunk swizzle (fm/wm drop out)
    const int akh  = (lane >> 4) & 1;           // A k-half
    const int br   = (lane & 7) + ((lane & 16) ? 8 : 0);  // B row within 16
    const int sw_b = (lane & 7) >> 1;           // B chunk swizzle
    const int bkh  = (lane & 8) ? 1 : 0;        // B k-half
    const int t0l  = lane & 15;
    const int cb3  = wn * 8 + ((lane & 16) ? 1 : 0);

    float acc[2][8][4];
    #pragma unroll
    for (int i = 0; i < 2; i++)
        #pragma unroll
        for (int j = 0; j < 8; j++)
            #pragma unroll
            for (int k = 0; k < 4; k++) acc[i][j][k] = 0.f;

    const int nIter = K >> 5;

    // prologue: prefetch stages 0,1
    load_stage(0, smbase);
    cp_commit();
    if (1 < nIter) load_stage(1, smbase + STAGE_BYTES);
    cp_commit();

    int slot = 0;       // slot of stage `it`
    int nslot = 2;      // slot for stage it+2
    for (int it = 0; it < nIter; ++it) {
        cp_wait<1>();             // stage `it` resident (it+1 may pend)
        __syncthreads();          // all warps done with stage it-1 (slot nslot)

        // prefetch stage it+2 into slot last read at iter it-1
        if (it + 2 < nIter)
            load_stage(it + 2, smbase + (uint32_t)nslot * STAGE_BYTES);
        cp_commit();

        const uint32_t sb = smbase + (uint32_t)slot * STAGE_BYTES;
        #pragma unroll
        for (int ks = 0; ks < 2; ++ks) {
            uint32_t a0r[2][4], a1r[2][4];
            #pragma unroll
            for (int fm = 0; fm < 2; ++fm) {
                uint32_t ao = sb
                    + (uint32_t)((wm * 32 + fm * 16 + ar) * 64
                                 + (((ks * 2 + akh) ^ sw_a) << 4));
                ldsm4(a0r[fm], ao);
                ldsm4(a1r[fm], ao + 8192);
            }
            #pragma unroll
            for (int fn2 = 0; fn2 < 4; ++fn2) {
                uint32_t b0r[4], b1r[4];
                if (BTRANS == 0) {
                    uint32_t bo = sb + 16384
                        + (uint32_t)((wn * 64 + fn2 * 16 + br) * 64
                                     + (((ks * 2 + bkh) ^ sw_b) << 4));
                    ldsm4(b0r, bo);
                    ldsm4(b1r, bo + 8192);
                } else {
                    int t = ks * 16 + t0l;
                    uint32_t bo = sb + 16384
                        + (uint32_t)(t * 256 + (((cb3 + fn2 * 2) ^ (t & 7)) * 16));
                    ldsm4t(b0r, bo);
                    ldsm4t(b1r, bo + 8192);
                }
                #pragma unroll
                for (int fm = 0; fm < 2; ++fm) {
                    mma16816(acc[fm][2*fn2],   a0r[fm], b0r);
                    mma16816(acc[fm][2*fn2],   a0r[fm], b1r);
                    mma16816(acc[fm][2*fn2],   a1r[fm], b0r);
                    mma16816(acc[fm][2*fn2+1], a0r[fm], b0r + 2);
                    mma16816(acc[fm][2*fn2+1], a0r[fm], b1r + 2);
                    mma16816(acc[fm][2*fn2+1], a1r[fm], b0r + 2);
                }
            }
        }

        slot  = (slot  == NSTAGES - 1) ? 0 : slot + 1;
        nslot = (nslot == NSTAGES - 1) ? 0 : nslot + 1;
    }

    // epilogue
    #pragma unroll
    for (int fm = 0; fm < 2; ++fm) {
        const int r0 = wm * 32 + fm * 16 + g;
        #pragma unroll
        for (int fn = 0; fn < 8; ++fn) {
            const int col = wn * 64 + fn * 8 + 2 * c;
            float bv0 = 0.f, bv1 = 0.f;
            if (HAS_BIAS) { bv0 = __ldg(&bias[col]); bv1 = __ldg(&bias[col + 1]); }
            float o0 = acc[fm][fn][0] * scale + bv0;
            float o1 = acc[fm][fn][1] * scale + bv1;
            float o2 = acc[fm][fn][2] * scale + bv0;
            float o3 = acc[fm][fn][3] * scale + bv1;
            if (GELU) { o0 = gelu_f(o0); o1 = gelu_f(o1); o2 = gelu_f(o2); o3 = gelu_f(o3); }
            const size_t off0 = (size_t)r0 * ldc + col;
            const size_t off1 = (size_t)(r0 + 8) * ldc + col;
            if (OUT_SPLIT) {
                st_split2(Ch, Cl, off0, o0, o1);
                st_split2(Ch, Cl, off1, o2, o3);
            } else {
                *reinterpret_cast<float2*>(Cf + off0) = make_float2(o0, o1);
                *reinterpret_cast<float2*>(Cf + off1) = make_float2(o2, o3);
            }
        }
    }
}

// ---------------------------------------------------------------------------
// Kernel wrappers
// ---------------------------------------------------------------------------
template<int GELU, int OUT_SPLIT>
__global__ __launch_bounds__(256, 2) void k_gemm(
    const bf16* __restrict__ A0, const bf16* __restrict__ A1,
    const bf16* __restrict__ B0, const bf16* __restrict__ B1,
    const float* __restrict__ bias,
    float* __restrict__ Cf, bf16* __restrict__ Ch, bf16* __restrict__ Cl,
    int M, int N, int K)
{
    const int bm = blockIdx.y * 128;
    const int bn = blockIdx.x * 128;
    const size_t aoff = (size_t)bm * K;
    const size_t boff = (size_t)bn * K;
    const size_t coff = (size_t)bm * N + bn;
    gemm128_body<GELU, 1, OUT_SPLIT, 0>(
        A0 + aoff, A1 + aoff, K, B0 + boff, B1 + boff, K,
        bias + bn, 1.0f,
        OUT_SPLIT ? nullptr : (Cf + coff),
        OUT_SPLIT ? (Ch + coff) : nullptr,
        OUT_SPLIT ? (Cl + coff) : nullptr,
        N, K);
}

__global__ __launch_bounds__(256, 2) void k_scores(
    const bf16* __restrict__ q0, const bf16* __restrict__ q1,
    float* __restrict__ scr)
{
    const int tt = blockIdx.x, st = blockIdx.y;
    if (tt > st) return;
    const int hd = blockIdx.z, b = hd >> 4, n = hd & 15;
    const size_t qoff = ((size_t)b * SEQ + (size_t)st * 128) * H3 + (size_t)n * HDIM;
    const size_t koff = ((size_t)b * SEQ + (size_t)tt * 128) * H3 + HID + (size_t)n * HDIM;
    float* C = scr + ((size_t)hd * SEQ + (size_t)st * 128) * SEQ + (size_t)tt * 128;
    gemm128_body<0, 0, 0, 0>(
        q0 + qoff, q1 + qoff, H3, q0 + koff, q1 + koff, H3,
        nullptr, 0.08838834764831845f, C, nullptr, nullptr, SEQ, HDIM);
}

__global__ __launch_bounds__(256, 2) void k_pv(
    const bf16* __restrict__ p0, const bf16* __restrict__ p1,
    const bf16* __restrict__ v0, const bf16* __restrict__ v1,
    bf16* __restrict__ ch, bf16* __restrict__ cl)
{
    const int st = blockIdx.x, hd = blockIdx.y, b = hd >> 4, n = hd & 15;
    const size_t poff = ((size_t)hd * SEQ + (size_t)st * 128) * SEQ;
    const size_t voff = (size_t)b * SEQ * H3 + 2 * HID + (size_t)n * HDIM;
    const size_t coff = ((size_t)b * SEQ + (size_t)st * 128) * HID + (size_t)n * HDIM;
    gemm128_body<0, 0, 1, 1>(
        p0 + poff, p1 + poff, SEQ, v0 + voff, v1 + voff, H3,
        nullptr, 1.0f, nullptr, ch + coff, cl + coff, HID, (st + 1) * 128);
}

// ---------------------------------------------------------------------------
// Causal softmax: fp32 scores -> split bf16 probs, zero-filled to tile end
// ---------------------------------------------------------------------------
__global__ __launch_bounds__(256) void softmax_split(
    const float* __restrict__ scr, bf16* __restrict__ p0, bf16* __restrict__ p1)
{
    const int s  = blockIdx.x;
    const int hd = blockIdx.y;
    const size_t rb = ((size_t)hd * SEQ + s) * SEQ;
    const float* row = scr + rb;
    const int len = s + 1;
    const int base = threadIdx.x * 4;

    float4 v = *reinterpret_cast<const float4*>(row + base);
    float e[4] = {v.x, v.y, v.z, v.w};
    float mx = -1e30f;
    #pragma unroll
    for (int j = 0; j < 4; j++) {
        if (base + j >= len) e[j] = -1e30f;
        mx = fmaxf(mx, e[j]);
    }
    mx = blockReduceMax256(mx);

    float sum = 0.f;
    #pragma unroll
    for (int j = 0; j < 4; j++) {
        e[j] = (base + j < len) ? expf(e[j] - mx) : 0.f;
        sum += e[j];
    }
    sum = blockReduceSum256(sum);
    const float inv = 1.0f / sum;

    const int tile_end = ((s >> 7) + 1) << 7;
    if (base < tile_end) {
        float o0 = e[0] * inv, o1 = e[1] * inv, o2 = e[2] * inv, o3 = e[3] * inv;
        st_split2(p0, p1, rb + base,     o0, o1);
        st_split2(p0, p1, rb + base + 2, o2, o3);
    }
}

// ---------------------------------------------------------------------------
// Host side
// ---------------------------------------------------------------------------
static float* symaddrf(const void* sym) {
    void* p = nullptr; cudaGetSymbolAddress(&p, sym); return (float*)p;
}
static bf16* symaddrb(const void* sym) {
    void* p = nullptr; cudaGetSymbolAddress(&p, sym); return (bf16*)p;
}
static void split_launch(const float* s, bf16* hi, bf16* lo, size_t n) {
    int n4 = (int)(n / 4);
    split_fp32_bf16<<<(n4 + 255) / 256, 256>>>(s, hi, lo, n4);
}

extern "C" void kernel_launch(void* const* d_in, const int* in_sizes, int n_in,
                              void* d_out, int out_size)
{
    const float* hidden  = (const float*)d_in[0];
    const float* qkv_w   = (const float*)d_in[2];
    const float* qkv_b   = (const float*)d_in[3];
    const float* dense_w = (const float*)d_in[4];
    const float* dense_b = (const float*)d_in[5];
    const float* mlp_w1  = (const float*)d_in[6];
    const float* mlp_b1  = (const float*)d_in[7];
    const float* mlp_w2  = (const float*)d_in[8];
    const float* mlp_b2  = (const float*)d_in[9];
    const float* ln_in_g   = (const float*)d_in[10];
    const float* ln_in_b   = (const float*)d_in[11];
    const float* ln_post_g = (const float*)d_in[12];
    const float* ln_post_b = (const float*)d_in[13];
    const float* ln_s1_g   = (const float*)d_in[14];
    const float* ln_s1_b   = (const float*)d_in[15];
    const float* ln_s2_g   = (const float*)d_in[16];
    const float* ln_s2_b   = (const float*)d_in[17];

    cudaFuncSetAttribute(k_gemm<0,0>, cudaFuncAttributeMaxDynamicSharedMemorySize, GEMM_SMEM_DYN);
    cudaFuncSetAttribute(k_gemm<0,1>, cudaFuncAttributeMaxDynamicSharedMemorySize, GEMM_SMEM_DYN);
    cudaFuncSetAttribute(k_gemm<1,1>, cudaFuncAttributeMaxDynamicSharedMemorySize, GEMM_SMEM_DYN);
    cudaFuncSetAttribute(k_scores,    cudaFuncAttributeMaxDynamicSharedMemorySize, GEMM_SMEM_DYN);
    cudaFuncSetAttribute(k_pv,        cudaFuncAttributeMaxDynamicSharedMemorySize, GEMM_SMEM_DYN);

    float* h   = symaddrf(g_h);
    float* att = symaddrf(g_att);
    float* h2  = symaddrf(g_h2);
    float* m2  = symaddrf(g_m2);
    float* scr = symaddrf(g_scr);
    bf16* a0 = symaddrb(g_a0);   bf16* a1 = symaddrb(g_a1);
    bf16* w0 = symaddrb(g_w0);   bf16* w1 = symaddrb(g_w1);
    bf16* q0 = symaddrb(g_qkv0); bf16* q1 = symaddrb(g_qkv1);
    bf16* p0 = symaddrb(g_p0);   bf16* p1 = symaddrb(g_p1);
    bf16* c0 = symaddrb(g_c0);   bf16* c1 = symaddrb(g_c1);
    bf16* m1h = symaddrb(g_m1h); bf16* m1l = symaddrb(g_m1l);
    float* out = (float*)d_out;

    for (int l = 0; l < LAYERS; l++) {
        const float* hin = (l == 0) ? hidden : h;
        const float* l_qkv_w   = qkv_w   + (size_t)l * H3 * HID;
        const float* l_qkv_b   = qkv_b   + (size_t)l * H3;
        const float* l_dense_w = dense_w + (size_t)l * HID * HID;
        const float* l_dense_b = dense_b + (size_t)l * HID;
        const float* l_w1      = mlp_w1  + (size_t)l * H4 * HID;
        const float* l_b1      = mlp_b1  + (size_t)l * H4;
        const float* l_w2      = mlp_w2  + (size_t)l * HID * H4;
        const float* l_b2      = mlp_b2  + (size_t)l * HID;

        // x = LN_in(h) -> split
        ln_split_kernel<<<ROWS, 256>>>(hin, ln_in_g + l*HID, ln_in_b + l*HID, a0, a1);

        // qkv = x @ qkv_w^T + b  -> split bf16
        split_launch(l_qkv_w, w0, w1, (size_t)H3 * HID);
        k_gemm<0,1><<<dim3(H3/128, ROWS/128), 256, GEMM_SMEM_DYN>>>(
            a0, a1, w0, w1, l_qkv_b, nullptr, q0, q1, ROWS, H3, HID);

        // attention on tensor cores
        k_scores<<<dim3(8, 8, NHEADS_TOT), 256, GEMM_SMEM_DYN>>>(q0, q1, scr);
        softmax_split<<<dim3(SEQ, NHEADS_TOT), 256>>>(scr, p0, p1);
        k_pv<<<dim3(8, NHEADS_TOT), 256, GEMM_SMEM_DYN>>>(p0, p1, q0, q1, c0, c1);

        // attn_out = ctx @ dense_w^T + b  (fp32)
        split_launch(l_dense_w, w0, w1, (size_t)HID * HID);
        k_gemm<0,0><<<dim3(HID/128, ROWS/128), 256, GEMM_SMEM_DYN>>>(
            c0, c1, w0, w1, l_dense_b, att, nullptr, nullptr, ROWS, HID, HID);

        // h2 = h + LN_s1(attn_out)
        ln_kernel<<<ROWS, 256>>>(att, ln_s1_g + l*HID, ln_s1_b + l*HID, hin, h2);

        // y = LN_post(h2) -> split
        ln_split_kernel<<<ROWS, 256>>>(h2, ln_post_g + l*HID, ln_post_b + l*HID, a0, a1);

        // m1 = gelu(y @ w1^T + b1) -> split
        split_launch(l_w1, w0, w1, (size_t)H4 * HID);
        k_gemm<1,1><<<dim3(H4/128, ROWS/128), 256, GEMM_SMEM_DYN>>>(
            a0, a1, w0, w1, l_b1, nullptr, m1h, m1l, ROWS, H4, HID);

        // m2 = m1 @ w2^T + b2 (fp32)
        split_launch(l_w2, w0, w1, (size_t)HID * H4);
        k_gemm<0,0><<<dim3(HID/128, ROWS/128), 256, GEMM_SMEM_DYN>>>(
            m1h, m1l, w0, w1, l_b2, m2, nullptr, nullptr, ROWS, HID, H4);

        // h = h2 + LN_s2(m2)
        ln_kernel<<<ROWS, 256>>>(m2, ln_s2_g + l*HID, ln_s2_b + l*HID, h2, h);
    }

    cudaMemcpyAsync(out, h, (size_t)ROWS * HID * sizeof(float),
                    cudaMemcpyDeviceToDevice, 0);
}

// round 7
// speedup vs baseline: 1.6110x; 1.3506x over previous
#include <cuda_runtime.h>
#include <cuda_fp16.h>
#include <math.h>
#include <stdint.h>

// Problem constants
#define LAYERS 2
#define BATCH  4
#define SEQ    1024
#define HID    2048
#define NHEAD  16
#define HDIM   128
#define H3     (3*HID)
#define H4     (4*HID)
#define ROWS   (BATCH*SEQ)
#define NHEADS_TOT (BATCH*NHEAD)
#define EPSV   1e-5f

typedef __half fp16;

// ---------------------------------------------------------------------------
// Scratch (device globals)
// ---------------------------------------------------------------------------
__device__ float g_h   [(size_t)ROWS*HID];
__device__ float g_att [(size_t)ROWS*HID];
__device__ float g_h2  [(size_t)ROWS*HID];
__device__ float g_m2  [(size_t)ROWS*HID];
__device__ float g_scr [(size_t)NHEADS_TOT*SEQ*SEQ];
// fp16 split buffers
__device__ fp16 g_a0 [(size_t)ROWS*HID];
__device__ fp16 g_a1 [(size_t)ROWS*HID];
__device__ fp16 g_w0 [(size_t)H4*HID];          // weight hi (only part needed)
__device__ fp16 g_qkv0[(size_t)ROWS*H3];
__device__ fp16 g_qkv1[(size_t)ROWS*H3];
__device__ fp16 g_p0 [(size_t)NHEADS_TOT*SEQ*SEQ];
__device__ fp16 g_p1 [(size_t)NHEADS_TOT*SEQ*SEQ];
__device__ fp16 g_c0 [(size_t)ROWS*HID];
__device__ fp16 g_c1 [(size_t)ROWS*HID];
__device__ fp16 g_m1h[(size_t)ROWS*H4];
__device__ fp16 g_m1l[(size_t)ROWS*H4];

// ---------------------------------------------------------------------------
// Helpers
// ---------------------------------------------------------------------------
__device__ __forceinline__ uint32_t smem_u32(const void* p) {
    uint32_t a;
    asm("{ .reg .u64 t; cvta.to.shared.u64 t, %1; cvt.u32.u64 %0, t; }"
        : "=r"(a) : "l"(p));
    return a;
}
__device__ __forceinline__ void cp16(uint32_t dst, const void* src) {
    asm volatile("cp.async.cg.shared.global [%0], [%1], 16;"
                 :: "r"(dst), "l"(src) : "memory");
}
__device__ __forceinline__ void cp_commit() {
    asm volatile("cp.async.commit_group;" ::: "memory");
}
template<int N> __device__ __forceinline__ void cp_wait() {
    asm volatile("cp.async.wait_group %0;" :: "n"(N) : "memory");
}
__device__ __forceinline__ void mma16816(float* d, const uint32_t* a, const uint32_t* b) {
    asm volatile(
        "mma.sync.aligned.m16n8k16.row.col.f32.f16.f16.f32 "
        "{%0,%1,%2,%3}, {%4,%5,%6,%7}, {%8,%9}, {%0,%1,%2,%3};"
        : "+f"(d[0]), "+f"(d[1]), "+f"(d[2]), "+f"(d[3])
        : "r"(a[0]), "r"(a[1]), "r"(a[2]), "r"(a[3]), "r"(b[0]), "r"(b[1]));
}
__device__ __forceinline__ void ldsm4(uint32_t* r, uint32_t addr) {
    asm volatile("ldmatrix.sync.aligned.m8n8.x4.shared.b16 {%0,%1,%2,%3}, [%4];"
                 : "=r"(r[0]), "=r"(r[1]), "=r"(r[2]), "=r"(r[3]) : "r"(addr));
}
__device__ __forceinline__ void ldsm4t(uint32_t* r, uint32_t addr) {
    asm volatile("ldmatrix.sync.aligned.m8n8.x4.trans.shared.b16 {%0,%1,%2,%3}, [%4];"
                 : "=r"(r[0]), "=r"(r[1]), "=r"(r[2]), "=r"(r[3]) : "r"(addr));
}
__device__ __forceinline__ float gelu_f(float x) {
    float inner = 0.7978845608028654f * x * (1.0f + 0.044715f * x * x);
    return 0.5f * x * (1.0f + tanhf(inner));
}
__device__ __forceinline__ void st_split2(fp16* H, fp16* L, size_t off, float x, float y) {
    fp16 hx = __float2half_rn(x), hy = __float2half_rn(y);
    fp16 lx = __float2half_rn(x - __half2float(hx));
    fp16 ly = __float2half_rn(y - __half2float(hy));
    *reinterpret_cast<__half2*>(H + off) = __halves2half2(hx, hy);
    *reinterpret_cast<__half2*>(L + off) = __halves2half2(lx, ly);
}

// ---------------------------------------------------------------------------
// Block reductions
// ---------------------------------------------------------------------------
__device__ __forceinline__ float blockReduceSum256(float v) {
    __shared__ float sm[8];
    int lane = threadIdx.x & 31, w = threadIdx.x >> 5;
    #pragma unroll
    for (int o = 16; o > 0; o >>= 1) v += __shfl_xor_sync(0xffffffffu, v, o);
    if (lane == 0) sm[w] = v;
    __syncthreads();
    float r = sm[0];
    #pragma unroll
    for (int i = 1; i < 8; i++) r += sm[i];
    __syncthreads();
    return r;
}
__device__ __forceinline__ float blockReduceMax256(float v) {
    __shared__ float sm[8];
    int lane = threadIdx.x & 31, w = threadIdx.x >> 5;
    #pragma unroll
    for (int o = 16; o > 0; o >>= 1) v = fmaxf(v, __shfl_xor_sync(0xffffffffu, v, o));
    if (lane == 0) sm[w] = v;
    __syncthreads();
    float r = sm[0];
    #pragma unroll
    for (int i = 1; i < 8; i++) r = fmaxf(r, sm[i]);
    __syncthreads();
    return r;
}

// ---------------------------------------------------------------------------
// LayerNorm variants
// ---------------------------------------------------------------------------
__global__ __launch_bounds__(256) void ln_kernel(
    const float* __restrict__ x, const float* __restrict__ gamma,
    const float* __restrict__ beta, const float* __restrict__ res,
    float* __restrict__ out)
{
    const int row = blockIdx.x;
    const int tid = threadIdx.x;
    const float* xr = x + (size_t)row * HID;

    float v[8];
    float s = 0.f;
    #pragma unroll
    for (int i = 0; i < 8; i++) { v[i] = xr[i*256 + tid]; s += v[i]; }
    s = blockReduceSum256(s);
    const float mean = s * (1.0f / HID);

    float q = 0.f;
    #pragma unroll
    for (int i = 0; i < 8; i++) { float d = v[i] - mean; q += d * d; }
    q = blockReduceSum256(q);
    const float rstd = rsqrtf(q * (1.0f / HID) + EPSV);

    float* orow = out + (size_t)row * HID;
    const float* rrow = res + (size_t)row * HID;
    #pragma unroll
    for (int i = 0; i < 8; i++) {
        int c = i*256 + tid;
        orow[c] = rrow[c] + (v[i] - mean) * rstd * gamma[c] + beta[c];
    }
}

__global__ __launch_bounds__(256) void ln_split_kernel(
    const float* __restrict__ x, const float* __restrict__ gamma,
    const float* __restrict__ beta, fp16* __restrict__ hi, fp16* __restrict__ lo)
{
    const int row = blockIdx.x;
    const int tid = threadIdx.x;
    const float* xr = x + (size_t)row * HID;
    const int cb = tid * 8;

    float v[8];
    *reinterpret_cast<float4*>(v)     = *reinterpret_cast<const float4*>(xr + cb);
    *reinterpret_cast<float4*>(v + 4) = *reinterpret_cast<const float4*>(xr + cb + 4);
    float s = 0.f;
    #pragma unroll
    for (int i = 0; i < 8; i++) s += v[i];
    s = blockReduceSum256(s);
    const float mean = s * (1.0f / HID);

    float q = 0.f;
    #pragma unroll
    for (int i = 0; i < 8; i++) { float d = v[i] - mean; q += d * d; }
    q = blockReduceSum256(q);
    const float rstd = rsqrtf(q * (1.0f / HID) + EPSV);

    const size_t ob = (size_t)row * HID + cb;
    #pragma unroll
    for (int i = 0; i < 8; i += 2) {
        float o0 = (v[i]   - mean) * rstd * gamma[cb+i]   + beta[cb+i];
        float o1 = (v[i+1] - mean) * rstd * gamma[cb+i+1] + beta[cb+i+1];
        st_split2(hi, lo, ob + i, o0, o1);
    }
}

// ---------------------------------------------------------------------------
// fp32 -> fp16 convert (weights: hi part only)
// ---------------------------------------------------------------------------
__global__ __launch_bounds__(256) void conv_fp32_fp16(
    const float* __restrict__ src, fp16* __restrict__ dst, int n4)
{
    int i = blockIdx.x * 256 + threadIdx.x;
    if (i >= n4) return;
    float4 v = reinterpret_cast<const float4*>(src)[i];
    __half2* dp = reinterpret_cast<__half2*>(dst);
    dp[2*i + 0] = __halves2half2(__float2half_rn(v.x), __float2half_rn(v.y));
    dp[2*i + 1] = __halves2half2(__float2half_rn(v.z), __float2half_rn(v.w));
}

// ---------------------------------------------------------------------------
// Common 128x128 split-2 fp16 mma body:
//   C = (A0+A1) @ B0^T  (exact in A; drops A@B1, |B1|/|B| ~ 2^-12)
// 4-stage cp.async circular pipeline, compact 64B rows, chunk-XOR swizzle,
// 24KB stages -> 96KB total, 2 CTAs/SM, ONE __syncthreads per BK=32 iter.
// Stage layout: A0 @0, A1 @8192, B0 @16384 (8KB tile slots).
// ---------------------------------------------------------------------------
#define STAGE_BYTES 24576
#define NSTAGES 4
#define GEMM_SMEM_DYN (NSTAGES*STAGE_BYTES)

template<int GELU, int HAS_BIAS, int OUT_SPLIT, int BTRANS>
__device__ __forceinline__ void gemm128_body(
    const fp16* __restrict__ A0b, const fp16* __restrict__ A1b, int lda,
    const fp16* __restrict__ B0b, int ldb,
    const float* __restrict__ bias, float scale,
    float* __restrict__ Cf, fp16* __restrict__ Ch, fp16* __restrict__ Cl,
    int ldc, int K)
{
    extern __shared__ uint32_t smw[];
    const uint32_t smbase = smem_u32(smw);

    const int tid = threadIdx.x;
    const int wid = tid >> 5, lane = tid & 31;
    const int wm = wid & 3, wn = wid >> 2;
    const int g = lane >> 2, c = lane & 3;

    const char* pA0 = (const char*)A0b;
    const char* pA1 = (const char*)A1b;
    const char* pB0 = (const char*)B0b;
    const size_t la = (size_t)lda * 2, lb = (size_t)ldb * 2;

    auto load_stage = [&](int it, uint32_t sb) {
        if (BTRANS == 0) {
            // 3 tiles x 128 rows x 4 chunks = 1536 cp.async
            #pragma unroll
            for (int i = 0; i < 6; i++) {
                int idx = tid + i * 256;
                int t  = idx >> 9;                 // 0..2
                int r  = (idx >> 2) & 127;
                int ch = idx & 3;
                const char* base = (t == 0) ? pA0 : (t == 1) ? pA1 : pB0;
                size_t stride = (t < 2) ? la : lb;
                cp16(sb + (uint32_t)(t * 8192 + r * 64 + ((ch ^ ((r >> 1) & 3)) << 4)),
                     base + (size_t)r * stride + (size_t)it * 64 + ch * 16);
            }
        } else {
            #pragma unroll
            for (int i = 0; i < 6; i++) {
                int idx = tid + i * 256;
                if (idx < 1024) {                  // P0/P1: 2 x 128 rows x 4 chunks
                    int sp = idx >> 9;
                    int r  = (idx >> 2) & 127;
                    int ch = idx & 3;
                    const char* base = sp ? pA1 : pA0;
                    cp16(sb + (uint32_t)(sp * 8192 + r * 64 + ((ch ^ ((r >> 1) & 3)) << 4)),
                         base + (size_t)r * la + (size_t)it * 64 + ch * 16);
                } else {                           // V hi: 32 rows x 16 chunks
                    int v2 = idx - 1024;
                    int r  = v2 >> 4;
                    int ch = v2 & 15;
                    cp16(sb + (uint32_t)(16384 + r * 256 + ((ch ^ (r & 7)) * 16)),
                         pB0 + (size_t)(it * 32 + r) * lb + ch * 16);
                }
            }
        }
    };

    // per-thread ldmatrix constants
    const int ar   = (lane & 15);
    const int sw_a = (ar >> 1) & 3;
    const int akh  = (lane >> 4) & 1;
    const int br   = (lane & 7) + ((lane & 16) ? 8 : 0);
    const int sw_b = (lane & 7) >> 1;
    const int bkh  = (lane & 8) ? 1 : 0;
    const int t0l  = lane & 15;
    const int cb3  = wn * 8 + ((lane & 16) ? 1 : 0);

    float acc[2][8][4];
    #pragma unroll
    for (int i = 0; i < 2; i++)
        #pragma unroll
        for (int j = 0; j < 8; j++)
            #pragma unroll
            for (int k = 0; k < 4; k++) acc[i][j][k] = 0.f;

    const int nIter = K >> 5;

    // prologue: prefetch up to 3 stages
    #pragma unroll
    for (int s = 0; s < NSTAGES - 1; s++) {
        if (s < nIter) load_stage(s, smbase + (uint32_t)s * STAGE_BYTES);
        cp_commit();
    }

    for (int it = 0; it < nIter; ++it) {
        cp_wait<NSTAGES - 2>();   // stage `it` resident
        __syncthreads();          // all warps done reading stage it-1's slot

        // prefetch stage it+3 into slot last read at iter it-1
        if (it + NSTAGES - 1 < nIter)
            load_stage(it + NSTAGES - 1,
                       smbase + (uint32_t)((it + NSTAGES - 1) & (NSTAGES - 1)) * STAGE_BYTES);
        cp_commit();

        const uint32_t sb = smbase + (uint32_t)(it & (NSTAGES - 1)) * STAGE_BYTES;
        #pragma unroll
        for (int ks = 0; ks < 2; ++ks) {
            uint32_t a0r[2][4], a1r[2][4];
            #pragma unroll
            for (int fm = 0; fm < 2; ++fm) {
                uint32_t ao = sb
                    + (uint32_t)((wm * 32 + fm * 16 + ar) * 64
                                 + (((ks * 2 + akh) ^ sw_a) << 4));
                ldsm4(a0r[fm], ao);
                ldsm4(a1r[fm], ao + 8192);
            }
            #pragma unroll
            for (int fn2 = 0; fn2 < 4; ++fn2) {
                uint32_t b0r[4];
                if (BTRANS == 0) {
                    uint32_t bo = sb + 16384
                        + (uint32_t)((wn * 64 + fn2 * 16 + br) * 64
                                     + (((ks * 2 + bkh) ^ sw_b) << 4));
                    ldsm4(b0r, bo);
                } else {
                    int t = ks * 16 + t0l;
                    uint32_t bo = sb + 16384
                        + (uint32_t)(t * 256 + (((cb3 + fn2 * 2) ^ (t & 7)) * 16));
                    ldsm4t(b0r, bo);
                }
                #pragma unroll
                for (int fm = 0; fm < 2; ++fm) {
                    mma16816(acc[fm][2*fn2],   a0r[fm], b0r);
                    mma16816(acc[fm][2*fn2],   a1r[fm], b0r);
                    mma16816(acc[fm][2*fn2+1], a0r[fm], b0r + 2);
                    mma16816(acc[fm][2*fn2+1], a1r[fm], b0r + 2);
                }
            }
        }
    }

    // epilogue
    #pragma unroll
    for (int fm = 0; fm < 2; ++fm) {
        const int r0 = wm * 32 + fm * 16 + g;
        #pragma unroll
        for (int fn = 0; fn < 8; ++fn) {
            const int col = wn * 64 + fn * 8 + 2 * c;
            float bv0 = 0.f, bv1 = 0.f;
            if (HAS_BIAS) { bv0 = __ldg(&bias[col]); bv1 = __ldg(&bias[col + 1]); }
            float o0 = acc[fm][fn][0] * scale + bv0;
            float o1 = acc[fm][fn][1] * scale + bv1;
            float o2 = acc[fm][fn][2] * scale + bv0;
            float o3 = acc[fm][fn][3] * scale + bv1;
            if (GELU) { o0 = gelu_f(o0); o1 = gelu_f(o1); o2 = gelu_f(o2); o3 = gelu_f(o3); }
            const size_t off0 = (size_t)r0 * ldc + col;
            const size_t off1 = (size_t)(r0 + 8) * ldc + col;
            if (OUT_SPLIT) {
                st_split2(Ch, Cl, off0, o0, o1);
                st_split2(Ch, Cl, off1, o2, o3);
            } else {
                *reinterpret_cast<float2*>(Cf + off0) = make_float2(o0, o1);
                *reinterpret_cast<float2*>(Cf + off1) = make_float2(o2, o3);
            }
        }
    }
}

// ---------------------------------------------------------------------------
// Kernel wrappers
// ---------------------------------------------------------------------------
template<int GELU, int OUT_SPLIT>
__global__ __launch_bounds__(256, 2) void k_gemm(
    const fp16* __restrict__ A0, const fp16* __restrict__ A1,
    const fp16* __restrict__ B0,
    const float* __restrict__ bias,
    float* __restrict__ Cf, fp16* __restrict__ Ch, fp16* __restrict__ Cl,
    int M, int N, int K)
{
    const int bm = blockIdx.y * 128;
    const int bn = blockIdx.x * 128;
    const size_t aoff = (size_t)bm * K;
    const size_t boff = (size_t)bn * K;
    const size_t coff = (size_t)bm * N + bn;
    gemm128_body<GELU, 1, OUT_SPLIT, 0>(
        A0 + aoff, A1 + aoff, K, B0 + boff, K,
        bias + bn, 1.0f,
        OUT_SPLIT ? nullptr : (Cf + coff),
        OUT_SPLIT ? (Ch + coff) : nullptr,
        OUT_SPLIT ? (Cl + coff) : nullptr,
        N, K);
}

__global__ __launch_bounds__(256, 2) void k_scores(
    const fp16* __restrict__ q0, const fp16* __restrict__ q1,
    float* __restrict__ scr)
{
    const int tt = blockIdx.x, st = blockIdx.y;
    if (tt > st) return;
    const int hd = blockIdx.z, b = hd >> 4, n = hd & 15;
    const size_t qoff = ((size_t)b * SEQ + (size_t)st * 128) * H3 + (size_t)n * HDIM;
    const size_t koff = ((size_t)b * SEQ + (size_t)tt * 128) * H3 + HID + (size_t)n * HDIM;
    float* C = scr + ((size_t)hd * SEQ + (size_t)st * 128) * SEQ + (size_t)tt * 128;
    gemm128_body<0, 0, 0, 0>(
        q0 + qoff, q1 + qoff, H3, q0 + koff, H3,
        nullptr, 0.08838834764831845f, C, nullptr, nullptr, SEQ, HDIM);
}

__global__ __launch_bounds__(256, 2) void k_pv(
    const fp16* __restrict__ p0, const fp16* __restrict__ p1,
    const fp16* __restrict__ v0,
    fp16* __restrict__ ch, fp16* __restrict__ cl)
{
    const int st = blockIdx.x, hd = blockIdx.y, b = hd >> 4, n = hd & 15;
    const size_t poff = ((size_t)hd * SEQ + (size_t)st * 128) * SEQ;
    const size_t voff = (size_t)b * SEQ * H3 + 2 * HID + (size_t)n * HDIM;
    const size_t coff = ((size_t)b * SEQ + (size_t)st * 128) * HID + (size_t)n * HDIM;
    gemm128_body<0, 0, 1, 1>(
        p0 + poff, p1 + poff, SEQ, v0 + voff, H3,
        nullptr, 1.0f, nullptr, ch + coff, cl + coff, HID, (st + 1) * 128);
}

// ---------------------------------------------------------------------------
// Causal softmax: fp32 scores -> split fp16 probs, zero-filled to tile end
// ---------------------------------------------------------------------------
__global__ __launch_bounds__(256) void softmax_split(
    const float* __restrict__ scr, fp16* __restrict__ p0, fp16* __restrict__ p1)
{
    const int s  = blockIdx.x;
    const int hd = blockIdx.y;
    const size_t rb = ((size_t)hd * SEQ + s) * SEQ;
    const float* row = scr + rb;
    const int len = s + 1;
    const int base = threadIdx.x * 4;

    float4 v = *reinterpret_cast<const float4*>(row + base);
    float e[4] = {v.x, v.y, v.z, v.w};
    float mx = -1e30f;
    #pragma unroll
    for (int j = 0; j < 4; j++) {
        if (base + j >= len) e[j] = -1e30f;
        mx = fmaxf(mx, e[j]);
    }
    mx = blockReduceMax256(mx);

    float sum = 0.f;
    #pragma unroll
    for (int j = 0; j < 4; j++) {
        e[j] = (base + j < len) ? expf(e[j] - mx) : 0.f;
        sum += e[j];
    }
    sum = blockReduceSum256(sum);
    const float inv = 1.0f / sum;

    const int tile_end = ((s >> 7) + 1) << 7;
    if (base < tile_end) {
        float o0 = e[0] * inv, o1 = e[1] * inv, o2 = e[2] * inv, o3 = e[3] * inv;
        st_split2(p0, p1, rb + base,     o0, o1);
        st_split2(p0, p1, rb + base + 2, o2, o3);
    }
}

// ---------------------------------------------------------------------------
// Host side
// ---------------------------------------------------------------------------
static float* symaddrf(const void* sym) {
    void* p = nullptr; cudaGetSymbolAddress(&p, sym); return (float*)p;
}
static fp16* symaddrh(const void* sym) {
    void* p = nullptr; cudaGetSymbolAddress(&p, sym); return (fp16*)p;
}
static void conv_launch(const float* s, fp16* dst, size_t n) {
    int n4 = (int)(n / 4);
    conv_fp32_fp16<<<(n4 + 255) / 256, 256>>>(s, dst, n4);
}

extern "C" void kernel_launch(void* const* d_in, const int* in_sizes, int n_in,
                              void* d_out, int out_size)
{
    const float* hidden  = (const float*)d_in[0];
    const float* qkv_w   = (const float*)d_in[2];
    const float* qkv_b   = (const float*)d_in[3];
    const float* dense_w = (const float*)d_in[4];
    const float* dense_b = (const float*)d_in[5];
    const float* mlp_w1  = (const float*)d_in[6];
    const float* mlp_b1  = (const float*)d_in[7];
    const float* mlp_w2  = (const float*)d_in[8];
    const float* mlp_b2  = (const float*)d_in[9];
    const float* ln_in_g   = (const float*)d_in[10];
    const float* ln_in_b   = (const float*)d_in[11];
    const float* ln_post_g = (const float*)d_in[12];
    const float* ln_post_b = (const float*)d_in[13];
    const float* ln_s1_g   = (const float*)d_in[14];
    const float* ln_s1_b   = (const float*)d_in[15];
    const float* ln_s2_g   = (const float*)d_in[16];
    const float* ln_s2_b   = (const float*)d_in[17];

    cudaFuncSetAttribute(k_gemm<0,0>, cudaFuncAttributeMaxDynamicSharedMemorySize, GEMM_SMEM_DYN);
    cudaFuncSetAttribute(k_gemm<0,1>, cudaFuncAttributeMaxDynamicSharedMemorySize, GEMM_SMEM_DYN);
    cudaFuncSetAttribute(k_gemm<1,1>, cudaFuncAttributeMaxDynamicSharedMemorySize, GEMM_SMEM_DYN);
    cudaFuncSetAttribute(k_scores,    cudaFuncAttributeMaxDynamicSharedMemorySize, GEMM_SMEM_DYN);
    cudaFuncSetAttribute(k_pv,        cudaFuncAttributeMaxDynamicSharedMemorySize, GEMM_SMEM_DYN);

    float* h   = symaddrf(g_h);
    float* att = symaddrf(g_att);
    float* h2  = symaddrf(g_h2);
    float* m2  = symaddrf(g_m2);
    float* scr = symaddrf(g_scr);
    fp16* a0 = symaddrh(g_a0);   fp16* a1 = symaddrh(g_a1);
    fp16* w0 = symaddrh(g_w0);
    fp16* q0 = symaddrh(g_qkv0); fp16* q1 = symaddrh(g_qkv1);
    fp16* p0 = symaddrh(g_p0);   fp16* p1 = symaddrh(g_p1);
    fp16* c0 = symaddrh(g_c0);   fp16* c1 = symaddrh(g_c1);
    fp16* m1h = symaddrh(g_m1h); fp16* m1l = symaddrh(g_m1l);
    float* out = (float*)d_out;

    for (int l = 0; l < LAYERS; l++) {
        const float* hin = (l == 0) ? hidden : h;
        const float* l_qkv_w   = qkv_w   + (size_t)l * H3 * HID;
        const float* l_qkv_b   = qkv_b   + (size_t)l * H3;
        const float* l_dense_w = dense_w + (size_t)l * HID * HID;
        const float* l_dense_b = dense_b + (size_t)l * HID;
        const float* l_w1      = mlp_w1  + (size_t)l * H4 * HID;
        const float* l_b1      = mlp_b1  + (size_t)l * H4;
        const float* l_w2      = mlp_w2  + (size_t)l * HID * H4;
        const float* l_b2      = mlp_b2  + (size_t)l * HID;

        // x = LN_in(h) -> split
        ln_split_kernel<<<ROWS, 256>>>(hin, ln_in_g + l*HID, ln_in_b + l*HID, a0, a1);

        // qkv = x @ qkv_w^T + b  -> split fp16
        conv_launch(l_qkv_w, w0, (size_t)H3 * HID);
        k_gemm<0,1><<<dim3(H3/128, ROWS/128), 256, GEMM_SMEM_DYN>>>(
            a0, a1, w0, l_qkv_b, nullptr, q0, q1, ROWS, H3, HID);

        // attention on tensor cores
        k_scores<<<dim3(8, 8, NHEADS_TOT), 256, GEMM_SMEM_DYN>>>(q0, q1, scr);
        softmax_split<<<dim3(SEQ, NHEADS_TOT), 256>>>(scr, p0, p1);
        k_pv<<<dim3(8, NHEADS_TOT), 256, GEMM_SMEM_DYN>>>(p0, p1, q0, c0, c1);

        // attn_out = ctx @ dense_w^T + b  (fp32)
        conv_launch(l_dense_w, w0, (size_t)HID * HID);
        k_gemm<0,0><<<dim3(HID/128, ROWS/128), 256, GEMM_SMEM_DYN>>>(
            c0, c1, w0, l_dense_b, att, nullptr, nullptr, ROWS, HID, HID);

        // h2 = h + LN_s1(attn_out)
        ln_kernel<<<ROWS, 256>>>(att, ln_s1_g + l*HID, ln_s1_b + l*HID, hin, h2);

        // y = LN_post(h2) -> split
        ln_split_kernel<<<ROWS, 256>>>(h2, ln_post_g + l*HID, ln_post_b + l*HID, a0, a1);

        // m1 = gelu(y @ w1^T + b1) -> split
        conv_launch(l_w1, w0, (size_t)H4 * HID);
        k_gemm<1,1><<<dim3(H4/128, ROWS/128), 256, GEMM_SMEM_DYN>>>(
            a0, a1, w0, l_b1, nullptr, m1h, m1l, ROWS, H4, HID);

        // m2 = m1 @ w2^T + b2 (fp32)
        conv_launch(l_w2, w0, (size_t)HID * H4);
        k_gemm<0,0><<<dim3(HID/128, ROWS/128), 256, GEMM_SMEM_DYN>>>(
            m1h, m1l, w0, l_b2, m2, nullptr, nullptr, ROWS, HID, H4);

        // h = h2 + LN_s2(m2)
        ln_kernel<<<ROWS, 256>>>(m2, ln_s2_g + l*HID, ln_s2_b + l*HID, h2, h);
    }

    cudaMemcpyAsync(out, h, (size_t)ROWS * HID * sizeof(float),
                    cudaMemcpyDeviceToDevice, 0);
}